// round 16
// baseline (speedup 1.0000x reference)
#include <cuda_runtime.h>
#include <cuda_bf16.h>
#include <math.h>

#define BB 8
#define HH 128
#define WW 128
#define CC 768
#define NB 8
#define BS 96
#define WF 65
#define LAMBDA 0.01f

#define C4F 0.70710678118654752440f
#define C8F 0.92387953251128675613f
#define S8F 0.38268343236508977173f

// Frequency-domain scratch (bf16 transport): [b][wf][h][c]
__device__ __nv_bfloat162 g_F[(size_t)BB * WF * HH * CC];
// Twiddles: g_tw[k] = exp(-2*pi*i*k/128), k=0..64
__device__ float2 g_tw[65];
// Pre-packed bf16x2 weight images: [n][6 mats][96 o][52 words]
// mats: 0=W1r, 1=W1i, 2=-W1i, 3=W2r, 4=W2i, 5=-W2i
__device__ __align__(16) unsigned g_Wp[(size_t)NB * 6 * 96 * 52];

__device__ __forceinline__ float2 cmul(float2 a, float2 b) {
    return make_float2(a.x * b.x - a.y * b.y, a.x * b.y + a.y * b.x);
}

__device__ __forceinline__ unsigned bf2(float hi, float lo) {
    unsigned r;
    asm("cvt.rn.bf16x2.f32 %0, %1, %2;" : "=r"(r) : "f"(hi), "f"(lo));
    return r;
}

// packed complex bf16x2 word <-> float2 (exact widening)
__device__ __forceinline__ float2 upk(unsigned w) {
    return make_float2(__uint_as_float(w << 16),
                       __uint_as_float(w & 0xFFFF0000u));
}
__device__ __forceinline__ unsigned pk(float2 v) { return bf2(v.y, v.x); }

__device__ __forceinline__ void mma16(float c[4], unsigned a0, unsigned a1,
                                      unsigned a2, unsigned a3,
                                      unsigned b0, unsigned b1) {
    asm volatile(
        "mma.sync.aligned.m16n8k16.row.col.f32.bf16.bf16.f32 "
        "{%0,%1,%2,%3}, {%4,%5,%6,%7}, {%8,%9}, {%0,%1,%2,%3};"
        : "+f"(c[0]), "+f"(c[1]), "+f"(c[2]), "+f"(c[3])
        : "r"(a0), "r"(a1), "r"(a2), "r"(a3), "r"(b0), "r"(b1));
}

__device__ __forceinline__ void ldsm4(unsigned& r0, unsigned& r1,
                                      unsigned& r2, unsigned& r3,
                                      unsigned addr) {
    asm volatile(
        "ldmatrix.sync.aligned.m8n8.x4.shared.b16 {%0,%1,%2,%3}, [%4];"
        : "=r"(r0), "=r"(r1), "=r"(r2), "=r"(r3)
        : "r"(addr));
}

__device__ __forceinline__ float sshrink(float v) {
    return v > LAMBDA ? v - LAMBDA : (v < -LAMBDA ? v + LAMBDA : 0.f);
}

__global__ void k_init_tw() {
    int i = threadIdx.x;
    if (i < 65) {
        double a = -2.0 * 3.14159265358979323846264338327950288 * (double)i / 128.0;
        g_tw[i] = make_float2((float)cos(a), (float)sin(a));
    }
}

// ---------------------------------------------------------------------------
// Pre-pack weights into the padded smem image (bf16x2, [o][i-word]), with
// pre-negated imaginary copies so the MLP needs no per-fragment sign flips.
// ---------------------------------------------------------------------------
__global__ void k_pack_w(const float* __restrict__ w1,
                         const float* __restrict__ w2) {
    const int n = blockIdx.x, t = threadIdx.x;
    const float* srcs[4] = {w1 + n * BS * BS, w1 + NB * BS * BS + n * BS * BS,
                            w2 + n * BS * BS, w2 + NB * BS * BS + n * BS * BS};
    unsigned* dst = g_Wp + (size_t)n * 6 * 96 * 52;
    for (int idx = t; idx < 96 * 52; idx += 256) {
        int o = idx / 52, iw = idx - o * 52;
        unsigned vr1 = 0u, vi1 = 0u, vr2 = 0u, vi2 = 0u;
        if (iw < 48) {
            int i0 = 2 * iw;
            vr1 = bf2(srcs[0][(i0 + 1) * 96 + o], srcs[0][i0 * 96 + o]);
            vi1 = bf2(srcs[1][(i0 + 1) * 96 + o], srcs[1][i0 * 96 + o]);
            vr2 = bf2(srcs[2][(i0 + 1) * 96 + o], srcs[2][i0 * 96 + o]);
            vi2 = bf2(srcs[3][(i0 + 1) * 96 + o], srcs[3][i0 * 96 + o]);
        }
        dst[0 * 4992 + idx] = vr1;
        dst[1 * 4992 + idx] = vi1;
        dst[2 * 4992 + idx] = vi1 ^ 0x80008000u;
        dst[3 * 4992 + idx] = vr2;
        dst[4 * 4992 + idx] = vi2;
        dst[5 * 4992 + idx] = vi2 ^ 0x80008000u;
    }
}

// ----- register butterflies -----
template <bool INV>
__device__ __forceinline__ float2 rot90(float2 v) {
    return INV ? make_float2(-v.y, v.x) : make_float2(v.y, -v.x);
}

template <bool INV>
__device__ __forceinline__ void bf4_0(float2& x0, float2& x1, float2& x2,
                                      float2& x3) {
    float2 y0 = make_float2(x0.x + x1.x, x0.y + x1.y);
    float2 y1 = make_float2(x0.x - x1.x, x0.y - x1.y);
    float2 y2 = make_float2(x2.x + x3.x, x2.y + x3.y);
    float2 y3 = make_float2(x2.x - x3.x, x2.y - x3.y);
    float2 u3 = rot90<INV>(y3);
    x0 = make_float2(y0.x + y2.x, y0.y + y2.y);
    x2 = make_float2(y0.x - y2.x, y0.y - y2.y);
    x1 = make_float2(y1.x + u3.x, y1.y + u3.y);
    x3 = make_float2(y1.x - u3.x, y1.y - u3.y);
}

template <bool INV>
__device__ __forceinline__ void bf8_0(float2* x) {
    bf4_0<INV>(x[0], x[1], x[2], x[3]);
    bf4_0<INV>(x[4], x[5], x[6], x[7]);
    const float I = INV ? 1.f : -1.f;
    const float2 t1 = make_float2(C4F, I * C4F);
    const float2 t3 = make_float2(-C4F, I * C4F);
    { float2 a = x[0], u = x[4];
      x[0] = make_float2(a.x + u.x, a.y + u.y);
      x[4] = make_float2(a.x - u.x, a.y - u.y); }
    { float2 a = x[1], u = cmul(x[5], t1);
      x[1] = make_float2(a.x + u.x, a.y + u.y);
      x[5] = make_float2(a.x - u.x, a.y - u.y); }
    { float2 a = x[2], u = rot90<INV>(x[6]);
      x[2] = make_float2(a.x + u.x, a.y + u.y);
      x[6] = make_float2(a.x - u.x, a.y - u.y); }
    { float2 a = x[3], u = cmul(x[7], t3);
      x[3] = make_float2(a.x + u.x, a.y + u.y);
      x[7] = make_float2(a.x - u.x, a.y - u.y); }
}

template <bool INV>
__device__ __forceinline__ void bf16pt(float2* x) {
    bf8_0<INV>(x);
    bf8_0<INV>(x + 8);
    const float I = INV ? 1.f : -1.f;
    const float2 w1 = make_float2(C8F, I * S8F);
    const float2 w2 = make_float2(C4F, I * C4F);
    const float2 w3 = make_float2(S8F, I * C8F);
    const float2 w5 = make_float2(-S8F, I * C8F);
    const float2 w6 = make_float2(-C4F, I * C4F);
    const float2 w7 = make_float2(-C8F, I * S8F);
#pragma unroll
    for (int m = 0; m < 8; m++) {
        float2 u;
        if (m == 0) u = x[8];
        else if (m == 1) u = cmul(x[9], w1);
        else if (m == 2) u = cmul(x[10], w2);
        else if (m == 3) u = cmul(x[11], w3);
        else if (m == 4) u = rot90<INV>(x[12]);
        else if (m == 5) u = cmul(x[13], w5);
        else if (m == 6) u = cmul(x[14], w6);
        else u = cmul(x[15], w7);
        float2 a = x[m];
        x[m] = make_float2(a.x + u.x, a.y + u.y);
        x[m + 8] = make_float2(a.x - u.x, a.y - u.y);
    }
}

// Generic radix-2^3 with provided twiddles (w[0]; w[1],w[2]; w[3..6]).
__device__ __forceinline__ void bf8(float2 x[8], const float2 w[7]) {
    float2 t1 = cmul(x[1], w[0]), t3 = cmul(x[3], w[0]);
    float2 y0 = make_float2(x[0].x + t1.x, x[0].y + t1.y);
    float2 y1 = make_float2(x[0].x - t1.x, x[0].y - t1.y);
    float2 y2 = make_float2(x[2].x + t3.x, x[2].y + t3.y);
    float2 y3 = make_float2(x[2].x - t3.x, x[2].y - t3.y);
    float2 u2 = cmul(y2, w[1]), u3 = cmul(y3, w[2]);
    x[0] = make_float2(y0.x + u2.x, y0.y + u2.y);
    x[2] = make_float2(y0.x - u2.x, y0.y - u2.y);
    x[1] = make_float2(y1.x + u3.x, y1.y + u3.y);
    x[3] = make_float2(y1.x - u3.x, y1.y - u3.y);
    float2 t5 = cmul(x[5], w[0]), t7 = cmul(x[7], w[0]);
    float2 z0 = make_float2(x[4].x + t5.x, x[4].y + t5.y);
    float2 z1 = make_float2(x[4].x - t5.x, x[4].y - t5.y);
    float2 z2 = make_float2(x[6].x + t7.x, x[6].y + t7.y);
    float2 z3 = make_float2(x[6].x - t7.x, x[6].y - t7.y);
    float2 v2 = cmul(z2, w[1]), v3 = cmul(z3, w[2]);
    x[4] = make_float2(z0.x + v2.x, z0.y + v2.y);
    x[6] = make_float2(z0.x - v2.x, z0.y - v2.y);
    x[5] = make_float2(z1.x + v3.x, z1.y + v3.y);
    x[7] = make_float2(z1.x - v3.x, z1.y - v3.y);
#pragma unroll
    for (int q = 0; q < 4; q++) {
        float2 u = cmul(x[q + 4], w[3 + q]);
        float2 a = x[q];
        x[q] = make_float2(a.x + u.x, a.y + u.y);
        x[q + 4] = make_float2(a.x - u.x, a.y - u.y);
    }
}

// ---------------------------------------------------------------------------
// Pass 1: real FFT length 128 along W (pack-in-pairs), 2 radix-8 passes.
// ---------------------------------------------------------------------------
__global__ __launch_bounds__(512, 2) void k_fwd_w(const float* __restrict__ x) {
    extern __shared__ float2 sm2[];
    float2* sz = sm2;               // [64][128]
    float2* stw = sm2 + 64 * 128;   // [65]
    const int t = threadIdx.x;
    if (t < 65) stw[t] = g_tw[t];
    const int cl = t & 127, q = t >> 7;
    const int b = blockIdx.z, h = blockIdx.y;
    const int c = blockIdx.x * 128 + cl;
    const float* xp = x + ((size_t)(b * HH + h) * WW) * CC + c;

#pragma unroll
    for (int rr = 0; rr < 2; rr++) {
        int j = q * 2 + rr;
        float2 xv[8];
#pragma unroll
        for (int m = 0; m < 8; m++) {
            int mm = __brev((unsigned)(j * 8 + m)) >> 26;
            xv[m] = make_float2(xp[(size_t)(2 * mm) * CC],
                                xp[(size_t)(2 * mm + 1) * CC]);
        }
        bf8_0<false>(xv);
#pragma unroll
        for (int m = 0; m < 8; m++) sz[(j * 8 + m) * 128 + cl] = xv[m];
    }
    __syncthreads();

#pragma unroll
    for (int rr = 0; rr < 2; rr++) {
        int j = q * 2 + rr;
        float2 w[7];
        w[0] = stw[j << 3];
        w[1] = stw[j << 2];
        w[2] = stw[(j + 8) << 2];
#pragma unroll
        for (int qq = 0; qq < 4; qq++) w[3 + qq] = stw[(j + qq * 8) << 1];
        float2 xv[8];
#pragma unroll
        for (int m = 0; m < 8; m++) xv[m] = sz[(j + m * 8) * 128 + cl];
        bf8(xv, w);
#pragma unroll
        for (int m = 0; m < 8; m++) sz[(j + m * 8) * 128 + cl] = xv[m];
    }
    __syncthreads();

    size_t base = ((size_t)b * WF * HH + h) * CC + c;
    const size_t ws = (size_t)HH * CC;
#pragma unroll
    for (int jj = 0; jj < 8; jj++) {
        int idx = q * 8 + jj;
        if (idx == 0) {
            float2 Z0 = sz[cl];
            g_F[base] = __float22bfloat162_rn(make_float2(Z0.x + Z0.y, 0.f));
            g_F[base + 64 * ws] = __float22bfloat162_rn(make_float2(Z0.x - Z0.y, 0.f));
            float2 Z32 = sz[32 * 128 + cl];
            g_F[base + 32 * ws] = __float22bfloat162_rn(make_float2(Z32.x, -Z32.y));
        } else {
            int k = idx;  // 1..31
            float2 Zk = sz[k * 128 + cl];
            float2 Zm = sz[(64 - k) * 128 + cl];
            float2 E = make_float2(0.5f * (Zk.x + Zm.x), 0.5f * (Zk.y - Zm.y));
            float2 D = make_float2(0.5f * (Zk.x - Zm.x), 0.5f * (Zk.y + Zm.y));
            float2 O = make_float2(D.y, -D.x);
            float2 p = cmul(stw[k], O);
            g_F[base + (size_t)k * ws] =
                __float22bfloat162_rn(make_float2(E.x + p.x, E.y + p.y));
            float2 Ec = make_float2(E.x, -E.y);
            float2 Oc = make_float2(O.x, -O.y);
            float2 qv = cmul(stw[64 - k], Oc);
            g_F[base + (size_t)(64 - k) * ws] =
                __float22bfloat162_rn(make_float2(Ec.x + qv.x, Ec.y + qv.y));
        }
    }
}

// ---------------------------------------------------------------------------
// Fused pass: FFT-H fwd + complex MLP + FFT-H inv. 256 threads, 2 CTAs/SM.
// smem: sA [128][100] | overlay (tile [128][100] OR 3 weight mats [96][52])
// | tw. No per-fragment sign flips (pre-negated -Wi staged).
// ---------------------------------------------------------------------------
__global__ __launch_bounds__(256, 2) void k_fused(const float* __restrict__ b1,
                                                  const float* __restrict__ b2) {
    extern __shared__ unsigned smu[];
    unsigned* sA = smu;                           // [128][100] words
    unsigned* sSH = smu + 12800;                  // overlay: tile or 3 mats
    unsigned* sWr = sSH;                          // [96][52]
    unsigned* sWi = sSH + 4992;                   // [96][52]
    unsigned* sWiN = sSH + 9984;                  // [96][52] = -Wi
    float2* stw = (float2*)(smu + 27776);         // [65]

    const int t = threadIdx.x;
    const int lane = t & 31, warp = t >> 5;
    if (t < 65) stw[t] = g_tw[t];
    const int n = blockIdx.x, wf = blockIdx.y, b = blockIdx.z;
    const size_t base = ((size_t)(b * WF + wf) * HH) * CC + n * BS;
    const unsigned* gFu = (const unsigned*)g_F;
    const uint4* wsrc = (const uint4*)(g_Wp + (size_t)n * 6 * 96 * 52);

    // -------- forward pass 1: radix-16 (k=0) from g_F -> packed tile --------
    __syncthreads();  // stw visible
#pragma unroll
    for (int rep = 0; rep < 3; rep++) {
        int idx = rep * 256 + t;
        int j = idx / 96, col = idx - j * 96;
        float2 xv[16];
#pragma unroll
        for (int m = 0; m < 16; m++) {
            int h = __brev((unsigned)(j * 16 + m)) >> 25;
            xv[m] = upk(gFu[base + (size_t)h * CC + col]);
        }
        bf16pt<false>(xv);
        unsigned* p = sSH + (j * 16) * 100 + col;
#pragma unroll
        for (int m = 0; m < 16; m++) p[m * 100] = pk(xv[m]);
    }
    __syncthreads();

    // -------- forward pass 2: radix-8, col pairs, writes A directly --------
    {
        const float s128 = 0.0078125f;
#pragma unroll
        for (int rep = 0; rep < 3; rep++) {
            int idx = rep * 256 + t;
            int j = idx / 48, w2i = idx - j * 48;
            float2 w[7];
            w[0] = stw[j << 2];
            w[1] = stw[j << 1];
            w[2] = stw[(j + 16) << 1];
#pragma unroll
            for (int qq = 0; qq < 4; qq++) w[3 + qq] = stw[j + qq * 16];
            float2 xa[8], xb[8];
#pragma unroll
            for (int m = 0; m < 8; m++) {
                int row = j + m * 16;
                uint2 v = *(uint2*)&sSH[row * 100 + 2 * w2i];
                xa[m] = upk(v.x);
                xb[m] = upk(v.y);
            }
            bf8(xa, w);
            bf8(xb, w);
#pragma unroll
            for (int m = 0; m < 8; m++) {
                int row = j + m * 16;
                sA[row * 100 + w2i] = bf2(xb[m].x * s128, xa[m].x * s128);
                sA[row * 100 + 48 + w2i] = bf2(xb[m].y * s128, xa[m].y * s128);
            }
        }
    }
    __syncthreads();  // tile consumed -> safe to overlay weights

    // Stage W1 triple {Wr, Wi, -Wi} over the tile region
    {
        uint4* dst = (uint4*)sWr;
        for (int idx = t; idx < 3744; idx += 256) dst[idx] = wsrc[idx];
    }
    __syncthreads();

    // ---------------- MLP ----------------
    const int mgrp = warp & 3, nh = warp >> 2;   // 8 warps: 4 x 2
    const int g = lane >> 2, tig = lane & 3;
    const int arow = mgrp * 32 + g;

    const unsigned sAaddr = (unsigned)__cvta_generic_to_shared(sA);
    const int matq = lane >> 3;
    const unsigned aBase0 = sAaddr +
        (unsigned)(((mgrp * 32 + (lane & 7) + (matq & 1) * 8) * 100 +
                    (matq >> 1) * 4) * 4);
    const unsigned aBase1 = aBase0 + 16u * 100u * 4u;
    const unsigned bOff0 = (unsigned)(((((matq >> 1) * 8 +
                                         (lane & 7)) * 52) + (matq & 1) * 4) * 4);
    const unsigned pStep = 16u * 52u * 4u;
    const unsigned wLo = (unsigned)__cvta_generic_to_shared((nh == 0) ? sWr : sWi);
    const unsigned wHi = (unsigned)__cvta_generic_to_shared((nh == 0) ? sWiN : sWr);

    float acc[2][12][4];

    // ===== layer 1 =====
    {
        const float* bp = (nh == 0) ? (b1 + n * BS) : (b1 + NB * BS + n * BS);
#pragma unroll
        for (int j = 0; j < 12; j++) {
            int cih = j * 8 + 2 * tig;
            float bv0 = bp[cih], bv1 = bp[cih + 1];
#pragma unroll
            for (int mt = 0; mt < 2; mt++) {
                acc[mt][j][0] = bv0; acc[mt][j][1] = bv1;
                acc[mt][j][2] = bv0; acc[mt][j][3] = bv1;
            }
        }
#pragma unroll 1
        for (int kc = 0; kc < 12; kc++) {
            unsigned a0, a1, a2, a3, a4, a5, a6, a7;
            ldsm4(a0, a1, a2, a3, aBase0 + kc * 32);
            ldsm4(a4, a5, a6, a7, aBase1 + kc * 32);
            unsigned wA = ((kc < 6) ? wLo + kc * 32 : wHi + (kc - 6) * 32) + bOff0;
#pragma unroll
            for (int p = 0; p < 6; p++) {
                unsigned r0, r1, r2, r3;
                ldsm4(r0, r1, r2, r3, wA + p * pStep);
                mma16(acc[0][2 * p], a0, a1, a2, a3, r0, r1);
                mma16(acc[1][2 * p], a4, a5, a6, a7, r0, r1);
                mma16(acc[0][2 * p + 1], a0, a1, a2, a3, r2, r3);
                mma16(acc[1][2 * p + 1], a4, a5, a6, a7, r2, r3);
            }
        }
    }
    // write relu(O) over A (packed bf16x2)
#pragma unroll
    for (int j = 0; j < 12; j++) {
        int wcol = nh * 48 + j * 4 + tig;
#pragma unroll
        for (int mt = 0; mt < 2; mt++) {
            int r0 = arow + 16 * mt;
            sA[r0 * 100 + wcol] =
                bf2(fmaxf(acc[mt][j][1], 0.f), fmaxf(acc[mt][j][0], 0.f));
            sA[(r0 + 8) * 100 + wcol] =
                bf2(fmaxf(acc[mt][j][3], 0.f), fmaxf(acc[mt][j][2], 0.f));
        }
    }
    __syncthreads();  // W1 reads + relu writes complete

    // Stage W2 triple {Wr, Wi, -Wi} over W1
    {
        uint4* dst = (uint4*)sWr;
        for (int idx = t; idx < 3744; idx += 256) dst[idx] = wsrc[3744 + idx];
    }
    __syncthreads();

    // ===== layer 2 =====
    {
        const float* bp = (nh == 0) ? (b2 + n * BS) : (b2 + NB * BS + n * BS);
#pragma unroll
        for (int j = 0; j < 12; j++) {
            int cih = j * 8 + 2 * tig;
            float bv0 = bp[cih], bv1 = bp[cih + 1];
#pragma unroll
            for (int mt = 0; mt < 2; mt++) {
                acc[mt][j][0] = bv0; acc[mt][j][1] = bv1;
                acc[mt][j][2] = bv0; acc[mt][j][3] = bv1;
            }
        }
#pragma unroll 1
        for (int kc = 0; kc < 12; kc++) {
            unsigned a0, a1, a2, a3, a4, a5, a6, a7;
            ldsm4(a0, a1, a2, a3, aBase0 + kc * 32);
            ldsm4(a4, a5, a6, a7, aBase1 + kc * 32);
            unsigned wA = ((kc < 6) ? wLo + kc * 32 : wHi + (kc - 6) * 32) + bOff0;
#pragma unroll
            for (int p = 0; p < 6; p++) {
                unsigned r0, r1, r2, r3;
                ldsm4(r0, r1, r2, r3, wA + p * pStep);
                mma16(acc[0][2 * p], a0, a1, a2, a3, r0, r1);
                mma16(acc[1][2 * p], a4, a5, a6, a7, r0, r1);
                mma16(acc[0][2 * p + 1], a0, a1, a2, a3, r2, r3);
                mma16(acc[1][2 * p + 1], a4, a5, a6, a7, r2, r3);
            }
        }
    }
    __syncthreads();  // W2 reads done -> safe to overlay tile

    // softshrink -> packed bf16 tile (bit-reversed rows), 16-bit stores
    {
        __nv_bfloat16* T16 = (__nv_bfloat16*)sSH;
#pragma unroll
        for (int j = 0; j < 12; j++) {
            int ch = j * 8 + 2 * tig;
#pragma unroll
            for (int mt = 0; mt < 2; mt++) {
                int r0 = arow + 16 * mt, r1 = r0 + 8;
                int br0 = __brev((unsigned)r0) >> 25;
                int br1 = __brev((unsigned)r1) >> 25;
                T16[br0 * 200 + 2 * ch + nh] =
                    __float2bfloat16_rn(sshrink(acc[mt][j][0]));
                T16[br0 * 200 + 2 * (ch + 1) + nh] =
                    __float2bfloat16_rn(sshrink(acc[mt][j][1]));
                T16[br1 * 200 + 2 * ch + nh] =
                    __float2bfloat16_rn(sshrink(acc[mt][j][2]));
                T16[br1 * 200 + 2 * (ch + 1) + nh] =
                    __float2bfloat16_rn(sshrink(acc[mt][j][3]));
            }
        }
    }
    __syncthreads();

    // -------- inverse pass 1: radix-16 (k=0), packed tile in place --------
#pragma unroll
    for (int rep = 0; rep < 3; rep++) {
        int idx = rep * 256 + t;
        int j = idx / 96, col = idx - j * 96;
        unsigned* p = sSH + (j * 16) * 100 + col;
        float2 xv[16];
#pragma unroll
        for (int m = 0; m < 16; m++) xv[m] = upk(p[m * 100]);
        bf16pt<true>(xv);
#pragma unroll
        for (int m = 0; m < 16; m++) p[m * 100] = pk(xv[m]);
    }
    __syncthreads();

    // -------- inverse pass 2: radix-8, scatter directly to g_F --------
#pragma unroll
    for (int rep = 0; rep < 6; rep++) {
        int idx = rep * 256 + t;
        int j = idx / 96, col = idx - j * 96;
        float2 w[7];
        w[0] = stw[j << 2];
        w[1] = stw[j << 1];
        w[2] = stw[(j + 16) << 1];
#pragma unroll
        for (int qq = 0; qq < 4; qq++) w[3 + qq] = stw[j + qq * 16];
#pragma unroll
        for (int m = 0; m < 7; m++) w[m].y = -w[m].y;
        float2 xv[8];
#pragma unroll
        for (int m = 0; m < 8; m++)
            xv[m] = upk(sSH[(j + m * 16) * 100 + col]);
        bf8(xv, w);
#pragma unroll
        for (int m = 0; m < 8; m++)
            g_F[base + (size_t)(j + m * 16) * CC + col] =
                __float22bfloat162_rn(xv[m]);
    }
}

// ---------------------------------------------------------------------------
// Pass 5: inverse real FFT length 128 along W + 1/128 scale + residual add.
// ---------------------------------------------------------------------------
__global__ __launch_bounds__(512, 2) void k_inv_w(const float* __restrict__ x,
                                                  float* __restrict__ out) {
    extern __shared__ float2 sm2[];
    float2* sz = sm2;               // [64][128]
    float2* stw = sm2 + 64 * 128;   // [65]
    const int t = threadIdx.x;
    if (t < 65) stw[t] = g_tw[t];
    __syncthreads();
    const int cl = t & 127, q = t >> 7;
    const int b = blockIdx.z, h = blockIdx.y;
    const int c = blockIdx.x * 128 + cl;
    size_t base = ((size_t)b * WF * HH + h) * CC + c;
    const size_t ws = (size_t)HH * CC;

#pragma unroll
    for (int jj = 0; jj < 8; jj++) {
        int idx = q * 8 + jj;
        if (idx == 0) {
            float2 X0 = __bfloat1622float2(g_F[base]);
            float2 X64 = __bfloat1622float2(g_F[base + 64 * ws]);
            sz[cl] = make_float2(X0.x + X64.x, X0.x - X64.x);  // imag dropped
            float2 X32 = __bfloat1622float2(g_F[base + 32 * ws]);
            sz[1 * 128 + cl] = make_float2(2.f * X32.x, -2.f * X32.y);
        } else {
            int k = idx;  // 1..31
            float2 Xk = __bfloat1622float2(g_F[base + (size_t)k * ws]);
            float2 Xm = __bfloat1622float2(g_F[base + (size_t)(64 - k) * ws]);
            float2 A = make_float2(Xk.x + Xm.x, Xk.y - Xm.y);
            float2 D = make_float2(Xk.x - Xm.x, Xk.y + Xm.y);
            float2 wc = make_float2(stw[k].x, -stw[k].y);
            float2 tv = cmul(wc, D);
            sz[(__brev((unsigned)k) >> 26) * 128 + cl] =
                make_float2(A.x - tv.y, A.y + tv.x);
            float2 A2 = make_float2(Xm.x + Xk.x, Xm.y - Xk.y);
            float2 D2 = make_float2(Xm.x - Xk.x, Xm.y + Xk.y);
            float2 wc2 = make_float2(stw[64 - k].x, -stw[64 - k].y);
            float2 t2 = cmul(wc2, D2);
            sz[(__brev((unsigned)(64 - k)) >> 26) * 128 + cl] =
                make_float2(A2.x - t2.y, A2.y + t2.x);
        }
    }
    __syncthreads();

#pragma unroll
    for (int s = 0; s <= 3; s += 3) {
        int hf = 1 << s;
#pragma unroll
        for (int rr = 0; rr < 2; rr++) {
            int j = q * 2 + rr;
            int k = j & (hf - 1);
            int i0 = ((j >> s) << (s + 3)) + k;
            float2 w[7];
            w[0] = stw[k << (6 - s)];
            w[1] = stw[k << (5 - s)];
            w[2] = stw[(k + hf) << (5 - s)];
#pragma unroll
            for (int qq = 0; qq < 4; qq++) w[3 + qq] = stw[(k + qq * hf) << (4 - s)];
#pragma unroll
            for (int m = 0; m < 7; m++) w[m].y = -w[m].y;
            float2 xv[8];
#pragma unroll
            for (int m = 0; m < 8; m++) xv[m] = sz[(i0 + m * hf) * 128 + cl];
            bf8(xv, w);
#pragma unroll
            for (int m = 0; m < 8; m++) sz[(i0 + m * hf) * 128 + cl] = xv[m];
        }
        __syncthreads();
    }

    const size_t xbase = ((size_t)(b * HH + h) * WW) * CC + c;
#pragma unroll
    for (int mm = 0; mm < 16; mm++) {
        int m = q * 16 + mm;
        float2 z = sz[m * 128 + cl];
        size_t i0 = xbase + (size_t)(2 * m) * CC;
        size_t i1 = xbase + (size_t)(2 * m + 1) * CC;
        out[i0] = z.x * (1.f / 128.f) + x[i0];
        out[i1] = z.y * (1.f / 128.f) + x[i1];
    }
}

// ---------------------------------------------------------------------------
extern "C" void kernel_launch(void* const* d_in, const int* in_sizes, int n_in,
                              void* d_out, int out_size) {
    const float* x  = (const float*)d_in[0];
    const float* w1 = (const float*)d_in[1];
    const float* b1 = (const float*)d_in[2];
    const float* w2 = (const float*)d_in[3];
    const float* b2 = (const float*)d_in[4];
    float* out = (float*)d_out;

    const size_t sm_fftw = (size_t)(64 * 128 + 65) * sizeof(float2);   // 66056
    const size_t sm_fus  = (size_t)(27776) * 4 + 65 * 8;               // 111624

    cudaFuncSetAttribute(k_fwd_w, cudaFuncAttributeMaxDynamicSharedMemorySize, (int)sm_fftw);
    cudaFuncSetAttribute(k_fused, cudaFuncAttributeMaxDynamicSharedMemorySize, (int)sm_fus);
    cudaFuncSetAttribute(k_inv_w, cudaFuncAttributeMaxDynamicSharedMemorySize, (int)sm_fftw);

    k_init_tw<<<1, 128>>>();
    k_pack_w<<<NB, 256>>>(w1, w2);
    k_fwd_w<<<dim3(6, 128, 8), 512, sm_fftw>>>(x);
    k_fused<<<dim3(8, 65, 8), 256, sm_fus>>>(b1, b2);
    k_inv_w<<<dim3(6, 128, 8), 512, sm_fftw>>>(x, out);
}

// round 17
// speedup vs baseline: 1.0445x; 1.0445x over previous
#include <cuda_runtime.h>
#include <cuda_bf16.h>
#include <math.h>

#define BB 8
#define HH 128
#define WW 128
#define CC 768
#define NB 8
#define BS 96
#define WF 65
#define LAMBDA 0.01f

#define C4F 0.70710678118654752440f
#define C8F 0.92387953251128675613f
#define S8F 0.38268343236508977173f

// Frequency-domain scratch (bf16 transport): [b][wf][h][c]
__device__ __nv_bfloat162 g_F[(size_t)BB * WF * HH * CC];
// Twiddles: g_tw[k] = exp(-2*pi*i*k/128), k=0..64
__device__ float2 g_tw[65];
// Pre-packed bf16x2 weight images: [n][4 mats][96 o][52 words]
// mats: 0=W1r, 1=W1i, 2=W2r, 3=W2i
__device__ __align__(16) unsigned g_Wp[(size_t)NB * 4 * 96 * 52];

__device__ __forceinline__ float2 cmul(float2 a, float2 b) {
    return make_float2(a.x * b.x - a.y * b.y, a.x * b.y + a.y * b.x);
}

__device__ __forceinline__ unsigned bf2(float hi, float lo) {
    unsigned r;
    asm("cvt.rn.bf16x2.f32 %0, %1, %2;" : "=r"(r) : "f"(hi), "f"(lo));
    return r;
}

// packed complex bf16x2 word <-> float2 (exact widening)
__device__ __forceinline__ float2 upk(unsigned w) {
    return make_float2(__uint_as_float(w << 16),
                       __uint_as_float(w & 0xFFFF0000u));
}
__device__ __forceinline__ unsigned pk(float2 v) { return bf2(v.y, v.x); }

__device__ __forceinline__ void mma16(float c[4], unsigned a0, unsigned a1,
                                      unsigned a2, unsigned a3,
                                      unsigned b0, unsigned b1) {
    asm volatile(
        "mma.sync.aligned.m16n8k16.row.col.f32.bf16.bf16.f32 "
        "{%0,%1,%2,%3}, {%4,%5,%6,%7}, {%8,%9}, {%0,%1,%2,%3};"
        : "+f"(c[0]), "+f"(c[1]), "+f"(c[2]), "+f"(c[3])
        : "r"(a0), "r"(a1), "r"(a2), "r"(a3), "r"(b0), "r"(b1));
}

__device__ __forceinline__ void ldsm4(unsigned& r0, unsigned& r1,
                                      unsigned& r2, unsigned& r3,
                                      unsigned addr) {
    asm volatile(
        "ldmatrix.sync.aligned.m8n8.x4.shared.b16 {%0,%1,%2,%3}, [%4];"
        : "=r"(r0), "=r"(r1), "=r"(r2), "=r"(r3)
        : "r"(addr));
}

__device__ __forceinline__ float sshrink(float v) {
    return v > LAMBDA ? v - LAMBDA : (v < -LAMBDA ? v + LAMBDA : 0.f);
}

__global__ void k_init_tw() {
    int i = threadIdx.x;
    if (i < 65) {
        double a = -2.0 * 3.14159265358979323846264338327950288 * (double)i / 128.0;
        g_tw[i] = make_float2((float)cos(a), (float)sin(a));
    }
}

// ---------------------------------------------------------------------------
// Pre-pack weights into the exact padded smem image (bf16x2, [o][i-word]).
// ---------------------------------------------------------------------------
__global__ void k_pack_w(const float* __restrict__ w1,
                         const float* __restrict__ w2) {
    const int n = blockIdx.x, t = threadIdx.x;
    const float* src[4] = {w1 + n * BS * BS, w1 + NB * BS * BS + n * BS * BS,
                           w2 + n * BS * BS, w2 + NB * BS * BS + n * BS * BS};
    unsigned* dst = g_Wp + (size_t)n * 4 * 96 * 52;
    for (int idx = t; idx < 96 * 52; idx += 256) {
        int o = idx / 52, iw = idx - o * 52;
#pragma unroll
        for (int m = 0; m < 4; m++) {
            unsigned v = 0u;
            if (iw < 48) {
                int i0 = 2 * iw;
                v = bf2(src[m][(i0 + 1) * 96 + o], src[m][i0 * 96 + o]);
            }
            dst[m * 96 * 52 + idx] = v;
        }
    }
}

// ----- register butterflies -----
template <bool INV>
__device__ __forceinline__ float2 rot90(float2 v) {
    return INV ? make_float2(-v.y, v.x) : make_float2(v.y, -v.x);
}

template <bool INV>
__device__ __forceinline__ void bf4_0(float2& x0, float2& x1, float2& x2,
                                      float2& x3) {
    float2 y0 = make_float2(x0.x + x1.x, x0.y + x1.y);
    float2 y1 = make_float2(x0.x - x1.x, x0.y - x1.y);
    float2 y2 = make_float2(x2.x + x3.x, x2.y + x3.y);
    float2 y3 = make_float2(x2.x - x3.x, x2.y - x3.y);
    float2 u3 = rot90<INV>(y3);
    x0 = make_float2(y0.x + y2.x, y0.y + y2.y);
    x2 = make_float2(y0.x - y2.x, y0.y - y2.y);
    x1 = make_float2(y1.x + u3.x, y1.y + u3.y);
    x3 = make_float2(y1.x - u3.x, y1.y - u3.y);
}

template <bool INV>
__device__ __forceinline__ void bf8_0(float2* x) {
    bf4_0<INV>(x[0], x[1], x[2], x[3]);
    bf4_0<INV>(x[4], x[5], x[6], x[7]);
    const float I = INV ? 1.f : -1.f;
    const float2 t1 = make_float2(C4F, I * C4F);
    const float2 t3 = make_float2(-C4F, I * C4F);
    { float2 a = x[0], u = x[4];
      x[0] = make_float2(a.x + u.x, a.y + u.y);
      x[4] = make_float2(a.x - u.x, a.y - u.y); }
    { float2 a = x[1], u = cmul(x[5], t1);
      x[1] = make_float2(a.x + u.x, a.y + u.y);
      x[5] = make_float2(a.x - u.x, a.y - u.y); }
    { float2 a = x[2], u = rot90<INV>(x[6]);
      x[2] = make_float2(a.x + u.x, a.y + u.y);
      x[6] = make_float2(a.x - u.x, a.y - u.y); }
    { float2 a = x[3], u = cmul(x[7], t3);
      x[3] = make_float2(a.x + u.x, a.y + u.y);
      x[7] = make_float2(a.x - u.x, a.y - u.y); }
}

template <bool INV>
__device__ __forceinline__ void bf16pt(float2* x) {
    bf8_0<INV>(x);
    bf8_0<INV>(x + 8);
    const float I = INV ? 1.f : -1.f;
    const float2 w1 = make_float2(C8F, I * S8F);
    const float2 w2 = make_float2(C4F, I * C4F);
    const float2 w3 = make_float2(S8F, I * C8F);
    const float2 w5 = make_float2(-S8F, I * C8F);
    const float2 w6 = make_float2(-C4F, I * C4F);
    const float2 w7 = make_float2(-C8F, I * S8F);
#pragma unroll
    for (int m = 0; m < 8; m++) {
        float2 u;
        if (m == 0) u = x[8];
        else if (m == 1) u = cmul(x[9], w1);
        else if (m == 2) u = cmul(x[10], w2);
        else if (m == 3) u = cmul(x[11], w3);
        else if (m == 4) u = rot90<INV>(x[12]);
        else if (m == 5) u = cmul(x[13], w5);
        else if (m == 6) u = cmul(x[14], w6);
        else u = cmul(x[15], w7);
        float2 a = x[m];
        x[m] = make_float2(a.x + u.x, a.y + u.y);
        x[m + 8] = make_float2(a.x - u.x, a.y - u.y);
    }
}

// Generic radix-2^3 with provided twiddles (w[0]; w[1],w[2]; w[3..6]).
__device__ __forceinline__ void bf8(float2 x[8], const float2 w[7]) {
    float2 t1 = cmul(x[1], w[0]), t3 = cmul(x[3], w[0]);
    float2 y0 = make_float2(x[0].x + t1.x, x[0].y + t1.y);
    float2 y1 = make_float2(x[0].x - t1.x, x[0].y - t1.y);
    float2 y2 = make_float2(x[2].x + t3.x, x[2].y + t3.y);
    float2 y3 = make_float2(x[2].x - t3.x, x[2].y - t3.y);
    float2 u2 = cmul(y2, w[1]), u3 = cmul(y3, w[2]);
    x[0] = make_float2(y0.x + u2.x, y0.y + u2.y);
    x[2] = make_float2(y0.x - u2.x, y0.y - u2.y);
    x[1] = make_float2(y1.x + u3.x, y1.y + u3.y);
    x[3] = make_float2(y1.x - u3.x, y1.y - u3.y);
    float2 t5 = cmul(x[5], w[0]), t7 = cmul(x[7], w[0]);
    float2 z0 = make_float2(x[4].x + t5.x, x[4].y + t5.y);
    float2 z1 = make_float2(x[4].x - t5.x, x[4].y - t5.y);
    float2 z2 = make_float2(x[6].x + t7.x, x[6].y + t7.y);
    float2 z3 = make_float2(x[6].x - t7.x, x[6].y - t7.y);
    float2 v2 = cmul(z2, w[1]), v3 = cmul(z3, w[2]);
    x[4] = make_float2(z0.x + v2.x, z0.y + v2.y);
    x[6] = make_float2(z0.x - v2.x, z0.y - v2.y);
    x[5] = make_float2(z1.x + v3.x, z1.y + v3.y);
    x[7] = make_float2(z1.x - v3.x, z1.y - v3.y);
#pragma unroll
    for (int q = 0; q < 4; q++) {
        float2 u = cmul(x[q + 4], w[3 + q]);
        float2 a = x[q];
        x[q] = make_float2(a.x + u.x, a.y + u.y);
        x[q + 4] = make_float2(a.x - u.x, a.y - u.y);
    }
}

// ---------------------------------------------------------------------------
// Pass 1: real FFT length 128 along W (pack-in-pairs), 2 radix-8 passes.
// Tile [64][64 c], 256 threads, 4 CTAs/SM: cl = t&63, q = t>>6.
// ---------------------------------------------------------------------------
__global__ __launch_bounds__(256, 4) void k_fwd_w(const float* __restrict__ x) {
    extern __shared__ float2 sm2[];
    float2* sz = sm2;               // [64][64]
    float2* stw = sm2 + 64 * 64;    // [65]
    const int t = threadIdx.x;
    if (t < 65) stw[t] = g_tw[t];
    const int cl = t & 63, q = t >> 6;
    const int b = blockIdx.z, h = blockIdx.y;
    const int c = blockIdx.x * 64 + cl;
    const float* xp = x + ((size_t)(b * HH + h) * WW) * CC + c;

#pragma unroll
    for (int rr = 0; rr < 2; rr++) {
        int j = q * 2 + rr;
        float2 xv[8];
#pragma unroll
        for (int m = 0; m < 8; m++) {
            int mm = __brev((unsigned)(j * 8 + m)) >> 26;
            xv[m] = make_float2(xp[(size_t)(2 * mm) * CC],
                                xp[(size_t)(2 * mm + 1) * CC]);
        }
        bf8_0<false>(xv);
#pragma unroll
        for (int m = 0; m < 8; m++) sz[(j * 8 + m) * 64 + cl] = xv[m];
    }
    __syncthreads();

#pragma unroll
    for (int rr = 0; rr < 2; rr++) {
        int j = q * 2 + rr;
        float2 w[7];
        w[0] = stw[j << 3];
        w[1] = stw[j << 2];
        w[2] = stw[(j + 8) << 2];
#pragma unroll
        for (int qq = 0; qq < 4; qq++) w[3 + qq] = stw[(j + qq * 8) << 1];
        float2 xv[8];
#pragma unroll
        for (int m = 0; m < 8; m++) xv[m] = sz[(j + m * 8) * 64 + cl];
        bf8(xv, w);
#pragma unroll
        for (int m = 0; m < 8; m++) sz[(j + m * 8) * 64 + cl] = xv[m];
    }
    __syncthreads();

    size_t base = ((size_t)b * WF * HH + h) * CC + c;
    const size_t ws = (size_t)HH * CC;
#pragma unroll
    for (int jj = 0; jj < 8; jj++) {
        int idx = q * 8 + jj;
        if (idx == 0) {
            float2 Z0 = sz[cl];
            g_F[base] = __float22bfloat162_rn(make_float2(Z0.x + Z0.y, 0.f));
            g_F[base + 64 * ws] = __float22bfloat162_rn(make_float2(Z0.x - Z0.y, 0.f));
            float2 Z32 = sz[32 * 64 + cl];
            g_F[base + 32 * ws] = __float22bfloat162_rn(make_float2(Z32.x, -Z32.y));
        } else {
            int k = idx;  // 1..31
            float2 Zk = sz[k * 64 + cl];
            float2 Zm = sz[(64 - k) * 64 + cl];
            float2 E = make_float2(0.5f * (Zk.x + Zm.x), 0.5f * (Zk.y - Zm.y));
            float2 D = make_float2(0.5f * (Zk.x - Zm.x), 0.5f * (Zk.y + Zm.y));
            float2 O = make_float2(D.y, -D.x);
            float2 p = cmul(stw[k], O);
            g_F[base + (size_t)k * ws] =
                __float22bfloat162_rn(make_float2(E.x + p.x, E.y + p.y));
            float2 Ec = make_float2(E.x, -E.y);
            float2 Oc = make_float2(O.x, -O.y);
            float2 qv = cmul(stw[64 - k], Oc);
            g_F[base + (size_t)(64 - k) * ws] =
                __float22bfloat162_rn(make_float2(Ec.x + qv.x, Ec.y + qv.y));
        }
    }
}

// ---------------------------------------------------------------------------
// Fused pass: FFT-H fwd + complex MLP + FFT-H inv. 256 threads, 2 CTAs/SM.
// smem overlay: sA [128][100] | sSH (tile [128][100] OR weight pair
// [2][96][52]) | tw. W1 staged after fwd FFT; W2 staged between layers.
// ---------------------------------------------------------------------------
__global__ __launch_bounds__(256, 2) void k_fused(const float* __restrict__ b1,
                                                  const float* __restrict__ b2) {
    extern __shared__ unsigned smu[];
    unsigned* sA = smu;                           // [128][100] words
    unsigned* sSH = smu + 12800;                  // [128][100] words (overlay)
    unsigned* sWr = sSH;                          // [96][52] (overlay view)
    unsigned* sWi = sSH + 4992;                   // [96][52]
    float2* stw = (float2*)(smu + 25600);         // [65]

    const int t = threadIdx.x;
    const int lane = t & 31, warp = t >> 5;
    if (t < 65) stw[t] = g_tw[t];
    const int n = blockIdx.x, wf = blockIdx.y, b = blockIdx.z;
    const size_t base = ((size_t)(b * WF + wf) * HH) * CC + n * BS;
    const unsigned* gFu = (const unsigned*)g_F;
    const uint4* wsrc = (const uint4*)(g_Wp + (size_t)n * 4 * 96 * 52);

    // -------- forward pass 1: radix-16 (k=0) from g_F -> packed tile --------
    __syncthreads();  // stw visible
#pragma unroll
    for (int rep = 0; rep < 3; rep++) {
        int idx = rep * 256 + t;
        int j = idx / 96, col = idx - j * 96;
        float2 xv[16];
#pragma unroll
        for (int m = 0; m < 16; m++) {
            int h = __brev((unsigned)(j * 16 + m)) >> 25;
            xv[m] = upk(gFu[base + (size_t)h * CC + col]);
        }
        bf16pt<false>(xv);
        unsigned* p = sSH + (j * 16) * 100 + col;
#pragma unroll
        for (int m = 0; m < 16; m++) p[m * 100] = pk(xv[m]);
    }
    __syncthreads();

    // -------- forward pass 2: radix-8, col pairs, writes A directly --------
    {
        const float s128 = 0.0078125f;
#pragma unroll
        for (int rep = 0; rep < 3; rep++) {
            int idx = rep * 256 + t;
            int j = idx / 48, w2i = idx - j * 48;
            float2 w[7];
            w[0] = stw[j << 2];
            w[1] = stw[j << 1];
            w[2] = stw[(j + 16) << 1];
#pragma unroll
            for (int qq = 0; qq < 4; qq++) w[3 + qq] = stw[j + qq * 16];
            float2 xa[8], xb[8];
#pragma unroll
            for (int m = 0; m < 8; m++) {
                int row = j + m * 16;
                uint2 v = *(uint2*)&sSH[row * 100 + 2 * w2i];
                xa[m] = upk(v.x);
                xb[m] = upk(v.y);
            }
            bf8(xa, w);
            bf8(xb, w);
#pragma unroll
            for (int m = 0; m < 8; m++) {
                int row = j + m * 16;
                sA[row * 100 + w2i] = bf2(xb[m].x * s128, xa[m].x * s128);
                sA[row * 100 + 48 + w2i] = bf2(xb[m].y * s128, xa[m].y * s128);
            }
        }
    }
    __syncthreads();  // tile consumed -> safe to overlay weights

    // Stage W1 (mats 0,1) over the tile region
    {
        uint4* dst = (uint4*)sWr;
        for (int idx = t; idx < 2496; idx += 256) dst[idx] = wsrc[idx];
    }
    __syncthreads();

    // ---------------- MLP ----------------
    const int mgrp = warp & 3, nh = warp >> 2;   // 8 warps: 4 x 2
    const int g = lane >> 2, tig = lane & 3;
    const int arow = mgrp * 32 + g;

    const unsigned sAaddr = (unsigned)__cvta_generic_to_shared(sA);
    const int matq = lane >> 3;
    const unsigned aBase0 = sAaddr +
        (unsigned)(((mgrp * 32 + (lane & 7) + (matq & 1) * 8) * 100 +
                    (matq >> 1) * 4) * 4);
    const unsigned aBase1 = aBase0 + 16u * 100u * 4u;
    const unsigned bOff0 = (unsigned)(((((matq >> 1) * 8 +
                                         (lane & 7)) * 52) + (matq & 1) * 4) * 4);
    const unsigned pStep = 16u * 52u * 4u;
    const unsigned wLo = (unsigned)__cvta_generic_to_shared((nh == 0) ? sWr : sWi);
    const unsigned wHi = (unsigned)__cvta_generic_to_shared((nh == 0) ? sWi : sWr);
    const unsigned sgnHi = (nh == 0) ? 0x80008000u : 0u;

    float acc[2][12][4];

    // ===== layer 1 =====
    {
        const float* bp = (nh == 0) ? (b1 + n * BS) : (b1 + NB * BS + n * BS);
#pragma unroll
        for (int j = 0; j < 12; j++) {
            int cih = j * 8 + 2 * tig;
            float bv0 = bp[cih], bv1 = bp[cih + 1];
#pragma unroll
            for (int mt = 0; mt < 2; mt++) {
                acc[mt][j][0] = bv0; acc[mt][j][1] = bv1;
                acc[mt][j][2] = bv0; acc[mt][j][3] = bv1;
            }
        }
#pragma unroll 1
        for (int kc = 0; kc < 12; kc++) {
            unsigned a0, a1, a2, a3, a4, a5, a6, a7;
            ldsm4(a0, a1, a2, a3, aBase0 + kc * 32);
            ldsm4(a4, a5, a6, a7, aBase1 + kc * 32);
            unsigned sgn = (kc < 6) ? 0u : sgnHi;
            unsigned wA = ((kc < 6) ? wLo + kc * 32 : wHi + (kc - 6) * 32) + bOff0;
#pragma unroll
            for (int p = 0; p < 6; p++) {
                unsigned r0, r1, r2, r3;
                ldsm4(r0, r1, r2, r3, wA + p * pStep);
                r0 ^= sgn; r1 ^= sgn; r2 ^= sgn; r3 ^= sgn;
                mma16(acc[0][2 * p], a0, a1, a2, a3, r0, r1);
                mma16(acc[1][2 * p], a4, a5, a6, a7, r0, r1);
                mma16(acc[0][2 * p + 1], a0, a1, a2, a3, r2, r3);
                mma16(acc[1][2 * p + 1], a4, a5, a6, a7, r2, r3);
            }
        }
    }
    // write relu(O) over A (packed bf16x2)
#pragma unroll
    for (int j = 0; j < 12; j++) {
        int wcol = nh * 48 + j * 4 + tig;
#pragma unroll
        for (int mt = 0; mt < 2; mt++) {
            int r0 = arow + 16 * mt;
            sA[r0 * 100 + wcol] =
                bf2(fmaxf(acc[mt][j][1], 0.f), fmaxf(acc[mt][j][0], 0.f));
            sA[(r0 + 8) * 100 + wcol] =
                bf2(fmaxf(acc[mt][j][3], 0.f), fmaxf(acc[mt][j][2], 0.f));
        }
    }
    __syncthreads();  // W1 reads + relu writes complete

    // Stage W2 (mats 2,3) over W1
    {
        uint4* dst = (uint4*)sWr;
        for (int idx = t; idx < 2496; idx += 256) dst[idx] = wsrc[2496 + idx];
    }
    __syncthreads();

    // ===== layer 2 =====
    {
        const float* bp = (nh == 0) ? (b2 + n * BS) : (b2 + NB * BS + n * BS);
#pragma unroll
        for (int j = 0; j < 12; j++) {
            int cih = j * 8 + 2 * tig;
            float bv0 = bp[cih], bv1 = bp[cih + 1];
#pragma unroll
            for (int mt = 0; mt < 2; mt++) {
                acc[mt][j][0] = bv0; acc[mt][j][1] = bv1;
                acc[mt][j][2] = bv0; acc[mt][j][3] = bv1;
            }
        }
#pragma unroll 1
        for (int kc = 0; kc < 12; kc++) {
            unsigned a0, a1, a2, a3, a4, a5, a6, a7;
            ldsm4(a0, a1, a2, a3, aBase0 + kc * 32);
            ldsm4(a4, a5, a6, a7, aBase1 + kc * 32);
            unsigned sgn = (kc < 6) ? 0u : sgnHi;
            unsigned wA = ((kc < 6) ? wLo + kc * 32 : wHi + (kc - 6) * 32) + bOff0;
#pragma unroll
            for (int p = 0; p < 6; p++) {
                unsigned r0, r1, r2, r3;
                ldsm4(r0, r1, r2, r3, wA + p * pStep);
                r0 ^= sgn; r1 ^= sgn; r2 ^= sgn; r3 ^= sgn;
                mma16(acc[0][2 * p], a0, a1, a2, a3, r0, r1);
                mma16(acc[1][2 * p], a4, a5, a6, a7, r0, r1);
                mma16(acc[0][2 * p + 1], a0, a1, a2, a3, r2, r3);
                mma16(acc[1][2 * p + 1], a4, a5, a6, a7, r2, r3);
            }
        }
    }
    __syncthreads();  // W2 reads done -> safe to overlay tile

    // softshrink -> packed bf16 tile (bit-reversed rows), 16-bit stores
    {
        __nv_bfloat16* T16 = (__nv_bfloat16*)sSH;
#pragma unroll
        for (int j = 0; j < 12; j++) {
            int ch = j * 8 + 2 * tig;
#pragma unroll
            for (int mt = 0; mt < 2; mt++) {
                int r0 = arow + 16 * mt, r1 = r0 + 8;
                int br0 = __brev((unsigned)r0) >> 25;
                int br1 = __brev((unsigned)r1) >> 25;
                T16[br0 * 200 + 2 * ch + nh] =
                    __float2bfloat16_rn(sshrink(acc[mt][j][0]));
                T16[br0 * 200 + 2 * (ch + 1) + nh] =
                    __float2bfloat16_rn(sshrink(acc[mt][j][1]));
                T16[br1 * 200 + 2 * ch + nh] =
                    __float2bfloat16_rn(sshrink(acc[mt][j][2]));
                T16[br1 * 200 + 2 * (ch + 1) + nh] =
                    __float2bfloat16_rn(sshrink(acc[mt][j][3]));
            }
        }
    }
    __syncthreads();

    // -------- inverse pass 1: radix-16 (k=0), packed tile in place --------
#pragma unroll
    for (int rep = 0; rep < 3; rep++) {
        int idx = rep * 256 + t;
        int j = idx / 96, col = idx - j * 96;
        unsigned* p = sSH + (j * 16) * 100 + col;
        float2 xv[16];
#pragma unroll
        for (int m = 0; m < 16; m++) xv[m] = upk(p[m * 100]);
        bf16pt<true>(xv);
#pragma unroll
        for (int m = 0; m < 16; m++) p[m * 100] = pk(xv[m]);
    }
    __syncthreads();

    // -------- inverse pass 2: radix-8, scatter directly to g_F --------
#pragma unroll
    for (int rep = 0; rep < 6; rep++) {
        int idx = rep * 256 + t;
        int j = idx / 96, col = idx - j * 96;
        float2 w[7];
        w[0] = stw[j << 2];
        w[1] = stw[j << 1];
        w[2] = stw[(j + 16) << 1];
#pragma unroll
        for (int qq = 0; qq < 4; qq++) w[3 + qq] = stw[j + qq * 16];
#pragma unroll
        for (int m = 0; m < 7; m++) w[m].y = -w[m].y;
        float2 xv[8];
#pragma unroll
        for (int m = 0; m < 8; m++)
            xv[m] = upk(sSH[(j + m * 16) * 100 + col]);
        bf8(xv, w);
#pragma unroll
        for (int m = 0; m < 8; m++)
            g_F[base + (size_t)(j + m * 16) * CC + col] =
                __float22bfloat162_rn(xv[m]);
    }
}

// ---------------------------------------------------------------------------
// Pass 5: inverse real FFT length 128 along W + 1/128 scale + residual add.
// Tile [64][64 c], 256 threads, 4 CTAs/SM.
// ---------------------------------------------------------------------------
__global__ __launch_bounds__(256, 4) void k_inv_w(const float* __restrict__ x,
                                                  float* __restrict__ out) {
    extern __shared__ float2 sm2[];
    float2* sz = sm2;               // [64][64]
    float2* stw = sm2 + 64 * 64;    // [65]
    const int t = threadIdx.x;
    if (t < 65) stw[t] = g_tw[t];
    __syncthreads();
    const int cl = t & 63, q = t >> 6;
    const int b = blockIdx.z, h = blockIdx.y;
    const int c = blockIdx.x * 64 + cl;
    size_t base = ((size_t)b * WF * HH + h) * CC + c;
    const size_t ws = (size_t)HH * CC;

#pragma unroll
    for (int jj = 0; jj < 8; jj++) {
        int idx = q * 8 + jj;
        if (idx == 0) {
            float2 X0 = __bfloat1622float2(g_F[base]);
            float2 X64 = __bfloat1622float2(g_F[base + 64 * ws]);
            sz[cl] = make_float2(X0.x + X64.x, X0.x - X64.x);  // imag dropped
            float2 X32 = __bfloat1622float2(g_F[base + 32 * ws]);
            sz[1 * 64 + cl] = make_float2(2.f * X32.x, -2.f * X32.y);
        } else {
            int k = idx;  // 1..31
            float2 Xk = __bfloat1622float2(g_F[base + (size_t)k * ws]);
            float2 Xm = __bfloat1622float2(g_F[base + (size_t)(64 - k) * ws]);
            float2 A = make_float2(Xk.x + Xm.x, Xk.y - Xm.y);
            float2 D = make_float2(Xk.x - Xm.x, Xk.y + Xm.y);
            float2 wc = make_float2(stw[k].x, -stw[k].y);
            float2 tv = cmul(wc, D);
            sz[(__brev((unsigned)k) >> 26) * 64 + cl] =
                make_float2(A.x - tv.y, A.y + tv.x);
            float2 A2 = make_float2(Xm.x + Xk.x, Xm.y - Xk.y);
            float2 D2 = make_float2(Xm.x - Xk.x, Xm.y + Xk.y);
            float2 wc2 = make_float2(stw[64 - k].x, -stw[64 - k].y);
            float2 t2 = cmul(wc2, D2);
            sz[(__brev((unsigned)(64 - k)) >> 26) * 64 + cl] =
                make_float2(A2.x - t2.y, A2.y + t2.x);
        }
    }
    __syncthreads();

#pragma unroll
    for (int s = 0; s <= 3; s += 3) {
        int hf = 1 << s;
#pragma unroll
        for (int rr = 0; rr < 2; rr++) {
            int j = q * 2 + rr;
            int k = j & (hf - 1);
            int i0 = ((j >> s) << (s + 3)) + k;
            float2 w[7];
            w[0] = stw[k << (6 - s)];
            w[1] = stw[k << (5 - s)];
            w[2] = stw[(k + hf) << (5 - s)];
#pragma unroll
            for (int qq = 0; qq < 4; qq++) w[3 + qq] = stw[(k + qq * hf) << (4 - s)];
#pragma unroll
            for (int m = 0; m < 7; m++) w[m].y = -w[m].y;
            float2 xv[8];
#pragma unroll
            for (int m = 0; m < 8; m++) xv[m] = sz[(i0 + m * hf) * 64 + cl];
            bf8(xv, w);
#pragma unroll
            for (int m = 0; m < 8; m++) sz[(i0 + m * hf) * 64 + cl] = xv[m];
        }
        __syncthreads();
    }

    const size_t xbase = ((size_t)(b * HH + h) * WW) * CC + c;
#pragma unroll
    for (int mm = 0; mm < 16; mm++) {
        int m = q * 16 + mm;
        float2 z = sz[m * 64 + cl];
        size_t i0 = xbase + (size_t)(2 * m) * CC;
        size_t i1 = xbase + (size_t)(2 * m + 1) * CC;
        out[i0] = z.x * (1.f / 128.f) + x[i0];
        out[i1] = z.y * (1.f / 128.f) + x[i1];
    }
}

// ---------------------------------------------------------------------------
extern "C" void kernel_launch(void* const* d_in, const int* in_sizes, int n_in,
                              void* d_out, int out_size) {
    const float* x  = (const float*)d_in[0];
    const float* w1 = (const float*)d_in[1];
    const float* b1 = (const float*)d_in[2];
    const float* w2 = (const float*)d_in[3];
    const float* b2 = (const float*)d_in[4];
    float* out = (float*)d_out;

    const size_t sm_fftw = (size_t)(64 * 64 + 65) * sizeof(float2);    // 33288
    const size_t sm_fus  = (size_t)(25600) * 4 + 65 * 8;               // 102920

    cudaFuncSetAttribute(k_fwd_w, cudaFuncAttributeMaxDynamicSharedMemorySize, (int)sm_fftw);
    cudaFuncSetAttribute(k_fused, cudaFuncAttributeMaxDynamicSharedMemorySize, (int)sm_fus);
    cudaFuncSetAttribute(k_inv_w, cudaFuncAttributeMaxDynamicSharedMemorySize, (int)sm_fftw);

    k_init_tw<<<1, 128>>>();
    k_pack_w<<<NB, 256>>>(w1, w2);
    k_fwd_w<<<dim3(12, 128, 8), 256, sm_fftw>>>(x);
    k_fused<<<dim3(8, 65, 8), 256, sm_fus>>>(b1, b2);
    k_inv_w<<<dim3(12, 128, 8), 256, sm_fftw>>>(x, out);
}